// round 4
// baseline (speedup 1.0000x reference)
#include <cuda_runtime.h>
#include <cuda_bf16.h>
#include <cstdint>
#include <cfloat>

#define BATCH 16
#define CH    512
#define NN    1681
#define NP    1682          /* padded row stride (even) */
#define CK    256
#define MQK   512
#define EPSV  1e-5f
#define SCALE 0.0625f       /* 256^-0.5 */

// ---------------- scratch ----------------
__device__ uint32_t       g_Wp[(CH / 2) * MQK];               // [CH/2][MQK] packed bf16 pairs
__device__ float          g_bias[MQK];
__device__ __nv_bfloat16  g_QKb[(size_t)BATCH * MQK * NP];    // bf16, padded rows
__device__ __nv_bfloat16  g_Pb[(size_t)BATCH * NN * NP];      // bf16 P, padded rows
__device__ float          g_minv[BATCH * NN];
__device__ float          g_s1[BATCH * NN];
__device__ float          g_s2[BATCH * NN];
__device__ float          g_inv[BATCH * NN];

// ---------------- helpers ----------------
__device__ __forceinline__ uint32_t packbf(float lo, float hi) {
    __nv_bfloat162 t = __floats2bfloat162_rn(lo, hi);
    return *reinterpret_cast<uint32_t*>(&t);
}

__device__ __forceinline__ void mma_bf16(float c[4], const uint32_t a[4], const uint32_t b[2]) {
    asm volatile(
        "mma.sync.aligned.m16n8k16.row.col.f32.bf16.bf16.f32 "
        "{%0,%1,%2,%3}, {%4,%5,%6,%7}, {%8,%9}, {%0,%1,%2,%3};\n"
        : "+f"(c[0]), "+f"(c[1]), "+f"(c[2]), "+f"(c[3])
        : "r"(a[0]), "r"(a[1]), "r"(a[2]), "r"(a[3]), "r"(b[0]), "r"(b[1]));
}

__device__ __forceinline__ void atomicMinFloat(float* addr, float value) {
    if (value >= 0.f) atomicMin((int*)addr, __float_as_int(value));
    else              atomicMax((unsigned int*)addr, __float_as_uint(value));
}

// ---------------- pack weights (bf16 pairs, [kp][m]) + reset stats ----------------
__global__ void pack_kernel(const float* __restrict__ Wq, const float* __restrict__ bq,
                            const float* __restrict__ Wk, const float* __restrict__ bk) {
    int idx = blockIdx.x * blockDim.x + threadIdx.x;
    if (idx < (CH / 2) * MQK) {
        int m = idx & (MQK - 1), kp = idx >> 9;
        float a = (m < CK) ? Wq[m * CH + 2 * kp]     : Wk[(m - CK) * CH + 2 * kp];
        float b = (m < CK) ? Wq[m * CH + 2 * kp + 1] : Wk[(m - CK) * CH + 2 * kp + 1];
        g_Wp[kp * MQK + m] = packbf(a, b);
    }
    if (idx < MQK) g_bias[idx] = (idx < CK) ? bq[idx] : bk[idx - CK];
    if (idx < BATCH * NN) {
        g_minv[idx] = FLT_MAX;
        g_s1[idx] = 0.f;
        g_s2[idx] = 0.f;
    }
}

// shared fragment compute: tile 128x128, 8 warps (4x2), per warp 2x8 m16n8k16
#define FRAG_MMA_LOOP(AS, BS)                                                  \
    for (int kk = 0; kk < 2; kk++) {                                           \
        const int kpb = kk * 8;                                                \
        uint32_t af[2][4], bfr[8][2];                                          \
        _Pragma("unroll")                                                      \
        for (int i = 0; i < 2; i++) {                                          \
            int mm = warp_m * 32 + i * 16 + r;                                 \
            af[i][0] = AS[kpb + cc][mm];                                       \
            af[i][1] = AS[kpb + cc][mm + 8];                                   \
            af[i][2] = AS[kpb + cc + 4][mm];                                   \
            af[i][3] = AS[kpb + cc + 4][mm + 8];                               \
        }                                                                      \
        _Pragma("unroll")                                                      \
        for (int j = 0; j < 8; j++) {                                          \
            int nn = warp_n * 64 + j * 8 + r;                                  \
            bfr[j][0] = BS[kpb + cc][nn];                                      \
            bfr[j][1] = BS[kpb + cc + 4][nn];                                  \
        }                                                                      \
        _Pragma("unroll")                                                      \
        for (int i = 0; i < 2; i++)                                            \
            _Pragma("unroll")                                                  \
            for (int j = 0; j < 8; j++) mma_bf16(acc[i][j], af[i], bfr[j]);    \
    }

// =====================================================================
// GEMM1: QK[b][m][n] = Wqk @ xf + bias    M=512, N=1681, K=512  (bf16 out)
// =====================================================================
__global__ __launch_bounds__(256) void gemm1_kernel(const float* __restrict__ x) {
    __shared__ uint32_t As_p[16][136];
    __shared__ uint32_t Bs_p[16][136];
    const int b  = blockIdx.z;
    const int m0 = blockIdx.y * 128;
    const int n0 = blockIdx.x * 128;
    const int tid = threadIdx.x;
    const int lane = tid & 31, wid = tid >> 5;
    const int warp_m = wid >> 1, warp_n = wid & 1;
    const int r = lane >> 2, cc = lane & 3;
    const float* xf = x + (size_t)b * CH * NN;

    float acc[2][8][4];
#pragma unroll
    for (int i = 0; i < 2; i++)
#pragma unroll
        for (int j = 0; j < 8; j++)
#pragma unroll
            for (int q = 0; q < 4; q++) acc[i][j][q] = 0.f;

    for (int k0 = 0; k0 < CH; k0 += 32) {
#pragma unroll
        for (int it = 0; it < 8; it++) {
            int li = tid + it * 256;
            int m = li & 127, kp = li >> 7;
            As_p[kp][m] = g_Wp[((k0 >> 1) + kp) * MQK + m0 + m];
        }
#pragma unroll
        for (int it = 0; it < 8; it++) {
            int li = tid + it * 256;
            int n = li & 127, kp = li >> 7;
            int gn = n0 + n, k = k0 + 2 * kp;
            float f0 = 0.f, f1 = 0.f;
            if (gn < NN) {
                f0 = xf[(size_t)k * NN + gn];
                f1 = xf[(size_t)(k + 1) * NN + gn];
            }
            Bs_p[kp][n] = packbf(f0, f1);
        }
        __syncthreads();
        FRAG_MMA_LOOP(As_p, Bs_p)
        __syncthreads();
    }

    __nv_bfloat16* outp = g_QKb + (size_t)b * MQK * NP;
#pragma unroll
    for (int i = 0; i < 2; i++)
#pragma unroll
        for (int h = 0; h < 2; h++) {
            int m = m0 + warp_m * 32 + i * 16 + r + h * 8;
            float bias = g_bias[m];
#pragma unroll
            for (int j = 0; j < 8; j++) {
                int n = n0 + warp_n * 64 + j * 8 + 2 * cc;
                if (n < NN)
                    outp[(size_t)m * NP + n]     = __float2bfloat16_rn(acc[i][j][2 * h] + bias);
                if (n + 1 < NN)
                    outp[(size_t)m * NP + n + 1] = __float2bfloat16_rn(acc[i][j][2 * h + 1] + bias);
            }
        }
}

// =====================================================================
// GEMM2: P[b][n][m] = (Q^T K)*scale*fg (bf16 out) + fused row stats
// =====================================================================
__global__ __launch_bounds__(256) void gemm2_kernel(const float* __restrict__ fg) {
    __shared__ uint32_t As_p[16][136];
    __shared__ uint32_t Bs_p[16][136];
    const int b  = blockIdx.z;
    const int n0 = blockIdx.y * 128;   // query rows
    const int m0 = blockIdx.x * 128;   // key cols
    const int tid = threadIdx.x;
    const int lane = tid & 31, wid = tid >> 5;
    const int warp_m = wid >> 1, warp_n = wid & 1;
    const int r = lane >> 2, cc = lane & 3;
    const __nv_bfloat16* Q  = g_QKb + (size_t)b * MQK * NP;
    const __nv_bfloat16* Kp = Q + (size_t)CK * NP;

    float acc[2][8][4];
#pragma unroll
    for (int i = 0; i < 2; i++)
#pragma unroll
        for (int j = 0; j < 8; j++)
#pragma unroll
            for (int q = 0; q < 4; q++) acc[i][j][q] = 0.f;

    for (int k0 = 0; k0 < CK; k0 += 32) {
#pragma unroll
        for (int it = 0; it < 8; it++) {
            int li = tid + it * 256;
            int col = li & 127, kp = li >> 7;
            int gn = n0 + col, k = k0 + 2 * kp;
            float f0 = 0.f, f1 = 0.f;
            if (gn < NN) {
                f0 = __bfloat162float(Q[(size_t)k * NP + gn]);
                f1 = __bfloat162float(Q[(size_t)(k + 1) * NP + gn]);
            }
            As_p[kp][col] = packbf(f0, f1);
        }
#pragma unroll
        for (int it = 0; it < 8; it++) {
            int li = tid + it * 256;
            int col = li & 127, kp = li >> 7;
            int gm = m0 + col, k = k0 + 2 * kp;
            float f0 = 0.f, f1 = 0.f;
            if (gm < NN) {
                f0 = __bfloat162float(Kp[(size_t)k * NP + gm]);
                f1 = __bfloat162float(Kp[(size_t)(k + 1) * NP + gm]);
            }
            Bs_p[kp][col] = packbf(f0, f1);
        }
        __syncthreads();
        FRAG_MMA_LOOP(As_p, Bs_p)
        __syncthreads();
    }

    const float* FG = fg + (size_t)b * NN * NN;
    __nv_bfloat16* Pp = g_Pb + (size_t)b * NN * NP;
#pragma unroll
    for (int i = 0; i < 2; i++)
#pragma unroll
        for (int h = 0; h < 2; h++) {
            int gn = n0 + warp_m * 32 + i * 16 + r + h * 8;
            bool rowvalid = gn < NN;
            size_t rowoff = (size_t)gn * NN;
            size_t prow   = (size_t)gn * NP;
            float mn = FLT_MAX, s1 = 0.f, s2 = 0.f;
#pragma unroll
            for (int j = 0; j < 8; j++) {
                int gm = m0 + warp_n * 64 + j * 8 + 2 * cc;
                if (rowvalid && gm < NN) {
                    float f0 = FG[rowoff + gm];
                    float p0 = acc[i][j][2 * h] * SCALE * f0;
                    Pp[prow + gm] = __float2bfloat16_rn(p0);
                    mn = fminf(mn, p0); s1 += p0 * f0; s2 += f0;
                }
                if (rowvalid && gm + 1 < NN) {
                    float f1 = FG[rowoff + gm + 1];
                    float p1 = acc[i][j][2 * h + 1] * SCALE * f1;
                    Pp[prow + gm + 1] = __float2bfloat16_rn(p1);
                    mn = fminf(mn, p1); s1 += p1 * f1; s2 += f1;
                }
            }
            mn = fminf(mn, __shfl_xor_sync(0xffffffffu, mn, 1));
            mn = fminf(mn, __shfl_xor_sync(0xffffffffu, mn, 2));
            s1 += __shfl_xor_sync(0xffffffffu, s1, 1);
            s1 += __shfl_xor_sync(0xffffffffu, s1, 2);
            s2 += __shfl_xor_sync(0xffffffffu, s2, 1);
            s2 += __shfl_xor_sync(0xffffffffu, s2, 2);
            if (cc == 0 && rowvalid) {
                atomicMinFloat(&g_minv[b * NN + gn], mn);
                atomicAdd(&g_s1[b * NN + gn], s1);
                atomicAdd(&g_s2[b * NN + gn], s2);
            }
        }
}

// ---------------- finalize ----------------
__global__ void finalize_kernel() {
    int idx = blockIdx.x * blockDim.x + threadIdx.x;
    if (idx < BATCH * NN)
        g_inv[idx] = 1.f / (g_s1[idx] - g_minv[idx] * g_s2[idx] + EPSV);
}

// =====================================================================
// GEMM3 (transposed): out[c][n] = gamma * sum_m xf[c][m]*sim_f[n][m] + x[c][n]
// M = c (512), N = n (1681), K = m (1681)
// =====================================================================
__global__ __launch_bounds__(256) void gemm3_kernel(const float* __restrict__ x,
                                                    const float* __restrict__ fg,
                                                    const float* __restrict__ bg,
                                                    const float* __restrict__ gamma,
                                                    float* __restrict__ out) {
    __shared__ uint32_t As_p[16][136];
    __shared__ uint32_t Bs_p[16][136];
    __shared__ float rMin[128], rInv[128];
    const int b  = blockIdx.z;
    const int c0 = blockIdx.x * 128;
    const int n0 = blockIdx.y * 128;
    const int tid = threadIdx.x;
    const int lane = tid & 31, wid = tid >> 5;
    const int warp_m = wid >> 1, warp_n = wid & 1;
    const int r = lane >> 2, cc = lane & 3;

    if (tid < 128) {
        int n = n0 + tid;
        rMin[tid] = (n < NN) ? g_minv[b * NN + n] : 0.f;
        rInv[tid] = (n < NN) ? g_inv[b * NN + n] : 0.f;
    }
    __syncthreads();

    const __nv_bfloat16* P = g_Pb + (size_t)b * NN * NP;
    const float* FG = fg + (size_t)b * NN * NN;
    const float* BG = bg + (size_t)b * NN * NN;
    const float* xf = x + (size_t)b * CH * NN;

    float acc[2][8][4];
#pragma unroll
    for (int i = 0; i < 2; i++)
#pragma unroll
        for (int j = 0; j < 8; j++)
#pragma unroll
            for (int q = 0; q < 4; q++) acc[i][j][q] = 0.f;

    for (int m0 = 0; m0 < NN; m0 += 32) {
        // A: xf[c][m] pairs along m
#pragma unroll
        for (int it = 0; it < 8; it++) {
            int li = tid + it * 256;
            int mp = li & 15, c = li >> 4;
            int gm = m0 + 2 * mp, gc = c0 + c;
            float f0 = 0.f, f1 = 0.f;
            if (gm < NN)     f0 = xf[(size_t)gc * NN + gm];
            if (gm + 1 < NN) f1 = xf[(size_t)gc * NN + gm + 1];
            As_p[mp][c] = packbf(f0, f1);
        }
        // B: sim_final[n][m] pairs along m (on the fly)
#pragma unroll
        for (int it = 0; it < 8; it++) {
            int li = tid + it * 256;
            int mp = li & 15, nl = li >> 4;
            int gm = m0 + 2 * mp, gn = n0 + nl;
            float v0 = 0.f, v1 = 0.f;
            if (gn < NN) {
                float mnv = rMin[nl], inv = rInv[nl];
                size_t prow = (size_t)gn * NP;
                size_t frow = (size_t)gn * NN;
                if (gm < NN)
                    v0 = (__bfloat162float(P[prow + gm]) - mnv) * FG[frow + gm] * inv + BG[frow + gm];
                if (gm + 1 < NN)
                    v1 = (__bfloat162float(P[prow + gm + 1]) - mnv) * FG[frow + gm + 1] * inv + BG[frow + gm + 1];
            }
            Bs_p[mp][nl] = packbf(v0, v1);
        }
        __syncthreads();
        FRAG_MMA_LOOP(As_p, Bs_p)
        __syncthreads();
    }

    const float g = gamma[0];
    float* outb = out + (size_t)b * CH * NN;
#pragma unroll
    for (int i = 0; i < 2; i++)
#pragma unroll
        for (int h = 0; h < 2; h++) {
            int gc = c0 + warp_m * 32 + i * 16 + r + h * 8;
            size_t rowoff = (size_t)gc * NN;
#pragma unroll
            for (int j = 0; j < 8; j++) {
                int gn = n0 + warp_n * 64 + j * 8 + 2 * cc;
                if (gn < NN)
                    outb[rowoff + gn]     = g * acc[i][j][2 * h]     + xf[rowoff + gn];
                if (gn + 1 < NN)
                    outb[rowoff + gn + 1] = g * acc[i][j][2 * h + 1] + xf[rowoff + gn + 1];
            }
        }
}

// ---------------- launch ----------------
extern "C" void kernel_launch(void* const* d_in, const int* in_sizes, int n_in,
                              void* d_out, int out_size) {
    const float* x     = (const float*)d_in[0];
    const float* fg    = (const float*)d_in[1];
    const float* bg    = (const float*)d_in[2];
    const float* Wq    = (const float*)d_in[3];
    const float* bq    = (const float*)d_in[4];
    const float* Wk    = (const float*)d_in[5];
    const float* bk    = (const float*)d_in[6];
    const float* gamma = (const float*)d_in[7];
    float* out = (float*)d_out;

    pack_kernel<<<((CH / 2) * MQK + 255) / 256, 256>>>(Wq, bq, Wk, bk);

    dim3 g1((NN + 127) / 128, MQK / 128, BATCH);
    gemm1_kernel<<<g1, 256>>>(x);

    dim3 g2((NN + 127) / 128, (NN + 127) / 128, BATCH);
    gemm2_kernel<<<g2, 256>>>(fg);

    finalize_kernel<<<(BATCH * NN + 255) / 256, 256>>>();

    dim3 g3(CH / 128, (NN + 127) / 128, BATCH);
    gemm3_kernel<<<g3, 256>>>(x, fg, bg, gamma, out);
}

// round 5
// speedup vs baseline: 1.2151x; 1.2151x over previous
#include <cuda_runtime.h>
#include <cstdint>
#include <cfloat>

#define BATCH 16
#define CH    512
#define NN    1681
#define CK    256
#define MQK   512
#define EPSV  1e-5f
#define SCALE 0.0625f   /* 256^-0.5 */

// ---------------- scratch ----------------
__device__ float g_Wqk[MQK * CH];
__device__ float g_bias[MQK];
__device__ float g_QK[(size_t)BATCH * MQK * NN];     // Q rows 0..255, K rows 256..511
__device__ float g_P[(size_t)BATCH * NN * NN];       // sim*scale*fg
__device__ float g_minv[BATCH * NN];
__device__ float g_s1[BATCH * NN];
__device__ float g_s2[BATCH * NN];

// ---------------- helpers ----------------
__device__ __forceinline__ uint32_t f2tf(float f) {
    uint32_t u;
    asm("cvt.rna.tf32.f32 %0, %1;" : "=r"(u) : "f"(f));
    return u;
}

__device__ __forceinline__ void mma_tf32(float c[4], const uint32_t a[4], const uint32_t b[2]) {
    asm volatile(
        "mma.sync.aligned.m16n8k8.row.col.f32.tf32.tf32.f32 "
        "{%0,%1,%2,%3}, {%4,%5,%6,%7}, {%8,%9}, {%0,%1,%2,%3};\n"
        : "+f"(c[0]), "+f"(c[1]), "+f"(c[2]), "+f"(c[3])
        : "r"(a[0]), "r"(a[1]), "r"(a[2]), "r"(a[3]), "r"(b[0]), "r"(b[1]));
}

__device__ __forceinline__ void atomicMinFloat(float* addr, float value) {
    if (value >= 0.f) atomicMin((int*)addr, __float_as_int(value));
    else              atomicMax((unsigned int*)addr, __float_as_uint(value));
}

// ---------------- pack weights + reset stats ----------------
__global__ void pack_kernel(const float* __restrict__ Wq, const float* __restrict__ bq,
                            const float* __restrict__ Wk, const float* __restrict__ bk) {
    int idx = blockIdx.x * blockDim.x + threadIdx.x;
    if (idx < MQK * CH) {
        int m = idx / CH, c = idx % CH;
        g_Wqk[idx] = (m < CK) ? Wq[m * CH + c] : Wk[(m - CK) * CH + c];
    }
    if (idx < MQK) g_bias[idx] = (idx < CK) ? bq[idx] : bk[idx - CK];
    if (idx < BATCH * NN) {
        g_minv[idx] = FLT_MAX;
        g_s1[idx] = 0.f;
        g_s2[idx] = 0.f;
    }
}

// fragment compute: tile 128x128, 8 warps (4x2), per warp 2x8 m16n8k8 over 16 k
#define FRAG_MMA_LOOP(AS, BS)                                                  \
    _Pragma("unroll")                                                          \
    for (int kk = 0; kk < 16; kk += 8) {                                       \
        uint32_t af[2][4], bfr[8][2];                                          \
        _Pragma("unroll")                                                      \
        for (int i = 0; i < 2; i++) {                                          \
            int mm = warp_m * 32 + i * 16 + r;                                 \
            af[i][0] = AS[kk + cc][mm];                                        \
            af[i][1] = AS[kk + cc][mm + 8];                                    \
            af[i][2] = AS[kk + cc + 4][mm];                                    \
            af[i][3] = AS[kk + cc + 4][mm + 8];                                \
        }                                                                      \
        _Pragma("unroll")                                                      \
        for (int j = 0; j < 8; j++) {                                          \
            int nn = warp_n * 64 + j * 8 + r;                                  \
            bfr[j][0] = BS[kk + cc][nn];                                       \
            bfr[j][1] = BS[kk + cc + 4][nn];                                   \
        }                                                                      \
        _Pragma("unroll")                                                      \
        for (int i = 0; i < 2; i++)                                            \
            _Pragma("unroll")                                                  \
            for (int j = 0; j < 8; j++) mma_tf32(acc[i][j], af[i], bfr[j]);    \
    }

// =====================================================================
// GEMM1: QK[b][m][n] = Wqk @ xf + bias    M=512, N=1681, K=512
// =====================================================================
__global__ __launch_bounds__(256) void gemm1_kernel(const float* __restrict__ x) {
    __shared__ uint32_t As[16][132];
    __shared__ uint32_t Bs[16][132];
    const int b  = blockIdx.z;
    const int m0 = blockIdx.y * 128;
    const int n0 = blockIdx.x * 128;
    const int tid = threadIdx.x;
    const int lane = tid & 31, wid = tid >> 5;
    const int warp_m = wid >> 1, warp_n = wid & 1;
    const int r = lane >> 2, cc = lane & 3;
    const float* xf = x + (size_t)b * CH * NN;

    float acc[2][8][4];
#pragma unroll
    for (int i = 0; i < 2; i++)
#pragma unroll
        for (int j = 0; j < 8; j++)
#pragma unroll
            for (int q = 0; q < 4; q++) acc[i][j][q] = 0.f;

    for (int k0 = 0; k0 < CH; k0 += 16) {
#pragma unroll
        for (int i = 0; i < 8; i++) {
            int li = tid + i * 256;
            int kc = li & 15, m = li >> 4;
            As[kc][m] = f2tf(g_Wqk[(m0 + m) * CH + k0 + kc]);
        }
#pragma unroll
        for (int i = 0; i < 8; i++) {
            int li = tid + i * 256;
            int n = li & 127, kc = li >> 7;
            int gn = n0 + n;
            Bs[kc][n] = f2tf(gn < NN ? xf[(size_t)(k0 + kc) * NN + gn] : 0.f);
        }
        __syncthreads();
        FRAG_MMA_LOOP(As, Bs)
        __syncthreads();
    }

    float* outp = g_QK + (size_t)b * MQK * NN;
#pragma unroll
    for (int i = 0; i < 2; i++)
#pragma unroll
        for (int h = 0; h < 2; h++) {
            int m = m0 + warp_m * 32 + i * 16 + r + h * 8;
            float bias = g_bias[m];
#pragma unroll
            for (int j = 0; j < 8; j++) {
                int n = n0 + warp_n * 64 + j * 8 + 2 * cc;
                if (n < NN)     outp[(size_t)m * NN + n]     = acc[i][j][2 * h]     + bias;
                if (n + 1 < NN) outp[(size_t)m * NN + n + 1] = acc[i][j][2 * h + 1] + bias;
            }
        }
}

// =====================================================================
// GEMM2: P[b][n][m] = (Q^T K)*scale*fg + fused row stats
// =====================================================================
__global__ __launch_bounds__(256) void gemm2_kernel(const float* __restrict__ fg) {
    __shared__ uint32_t As[16][132];
    __shared__ uint32_t Bs[16][132];
    const int b  = blockIdx.z;
    const int n0 = blockIdx.y * 128;
    const int m0 = blockIdx.x * 128;
    const int tid = threadIdx.x;
    const int lane = tid & 31, wid = tid >> 5;
    const int warp_m = wid >> 1, warp_n = wid & 1;
    const int r = lane >> 2, cc = lane & 3;
    const float* Q  = g_QK + (size_t)b * MQK * NN;
    const float* Kp = Q + (size_t)CK * NN;

    float acc[2][8][4];
#pragma unroll
    for (int i = 0; i < 2; i++)
#pragma unroll
        for (int j = 0; j < 8; j++)
#pragma unroll
            for (int q = 0; q < 4; q++) acc[i][j][q] = 0.f;

    for (int k0 = 0; k0 < CK; k0 += 16) {
#pragma unroll
        for (int i = 0; i < 8; i++) {
            int li = tid + i * 256;
            int n = li & 127, kc = li >> 7;
            int gn = n0 + n;
            As[kc][n] = f2tf(gn < NN ? Q[(size_t)(k0 + kc) * NN + gn] : 0.f);
        }
#pragma unroll
        for (int i = 0; i < 8; i++) {
            int li = tid + i * 256;
            int m = li & 127, kc = li >> 7;
            int gm = m0 + m;
            Bs[kc][m] = f2tf(gm < NN ? Kp[(size_t)(k0 + kc) * NN + gm] : 0.f);
        }
        __syncthreads();
        FRAG_MMA_LOOP(As, Bs)
        __syncthreads();
    }

    const float* FG = fg + (size_t)b * NN * NN;
    float* Pp = g_P + (size_t)b * NN * NN;
#pragma unroll
    for (int i = 0; i < 2; i++)
#pragma unroll
        for (int h = 0; h < 2; h++) {
            int gn = n0 + warp_m * 32 + i * 16 + r + h * 8;
            bool rowvalid = gn < NN;
            size_t rowoff = (size_t)gn * NN;
            float mn = FLT_MAX, s1 = 0.f, s2 = 0.f;
#pragma unroll
            for (int j = 0; j < 8; j++) {
                int gm = m0 + warp_n * 64 + j * 8 + 2 * cc;
                if (rowvalid && gm < NN) {
                    float f = FG[rowoff + gm];
                    float p = acc[i][j][2 * h] * SCALE * f;
                    Pp[rowoff + gm] = p;
                    mn = fminf(mn, p); s1 += p * f; s2 += f;
                }
                if (rowvalid && gm + 1 < NN) {
                    float f = FG[rowoff + gm + 1];
                    float p = acc[i][j][2 * h + 1] * SCALE * f;
                    Pp[rowoff + gm + 1] = p;
                    mn = fminf(mn, p); s1 += p * f; s2 += f;
                }
            }
            mn = fminf(mn, __shfl_xor_sync(0xffffffffu, mn, 1));
            mn = fminf(mn, __shfl_xor_sync(0xffffffffu, mn, 2));
            s1 += __shfl_xor_sync(0xffffffffu, s1, 1);
            s1 += __shfl_xor_sync(0xffffffffu, s1, 2);
            s2 += __shfl_xor_sync(0xffffffffu, s2, 1);
            s2 += __shfl_xor_sync(0xffffffffu, s2, 2);
            if (cc == 0 && rowvalid) {
                atomicMinFloat(&g_minv[b * NN + gn], mn);
                atomicAdd(&g_s1[b * NN + gn], s1);
                atomicAdd(&g_s2[b * NN + gn], s2);
            }
        }
}

// =====================================================================
// GEMM3 (transposed): out[c][n] = gamma * sum_m xf[c][m]*sim_f[n][m] + x[c][n]
// M = c (512), N = n (1681), K = m (1681); sim_final on the fly; inv fused.
// =====================================================================
__global__ __launch_bounds__(256) void gemm3_kernel(const float* __restrict__ x,
                                                    const float* __restrict__ fg,
                                                    const float* __restrict__ bg,
                                                    const float* __restrict__ gamma,
                                                    float* __restrict__ out) {
    __shared__ uint32_t As[16][132];
    __shared__ uint32_t Bs[16][132];
    __shared__ float rMin[128], rInv[128];
    const int b  = blockIdx.z;
    const int c0 = blockIdx.x * 128;
    const int n0 = blockIdx.y * 128;
    const int tid = threadIdx.x;
    const int lane = tid & 31, wid = tid >> 5;
    const int warp_m = wid >> 1, warp_n = wid & 1;
    const int r = lane >> 2, cc = lane & 3;

    if (tid < 128) {
        int n = n0 + tid;
        if (n < NN) {
            float mn = g_minv[b * NN + n];
            rMin[tid] = mn;
            rInv[tid] = 1.f / (g_s1[b * NN + n] - mn * g_s2[b * NN + n] + EPSV);
        } else {
            rMin[tid] = 0.f;
            rInv[tid] = 0.f;
        }
    }
    __syncthreads();

    const float* P  = g_P + (size_t)b * NN * NN;
    const float* FG = fg + (size_t)b * NN * NN;
    const float* BG = bg + (size_t)b * NN * NN;
    const float* xf = x + (size_t)b * CH * NN;

    float acc[2][8][4];
#pragma unroll
    for (int i = 0; i < 2; i++)
#pragma unroll
        for (int j = 0; j < 8; j++)
#pragma unroll
            for (int q = 0; q < 4; q++) acc[i][j][q] = 0.f;

    for (int m0 = 0; m0 < NN; m0 += 16) {
        // A: xf[c0+c][m0+kc]  (lanes consecutive in kc -> coalesced along m)
#pragma unroll
        for (int i = 0; i < 8; i++) {
            int li = tid + i * 256;
            int kc = li & 15, c = li >> 4;
            int gm = m0 + kc;
            As[kc][c] = f2tf(gm < NN ? xf[(size_t)(c0 + c) * NN + gm] : 0.f);
        }
        // B: sim_final[n0+nl][m0+kc] on the fly (lanes consecutive in kc -> coalesced)
#pragma unroll
        for (int i = 0; i < 8; i++) {
            int li = tid + i * 256;
            int kc = li & 15, nl = li >> 4;
            int gn = n0 + nl, gm = m0 + kc;
            float v = 0.f;
            if (gn < NN && gm < NN) {
                size_t a = (size_t)gn * NN + gm;
                v = (P[a] - rMin[nl]) * FG[a] * rInv[nl] + BG[a];
            }
            Bs[kc][nl] = f2tf(v);
        }
        __syncthreads();
        FRAG_MMA_LOOP(As, Bs)
        __syncthreads();
    }

    const float g = gamma[0];
    float* outb = out + (size_t)b * CH * NN;
#pragma unroll
    for (int i = 0; i < 2; i++)
#pragma unroll
        for (int h = 0; h < 2; h++) {
            int gc = c0 + warp_m * 32 + i * 16 + r + h * 8;
            size_t rowoff = (size_t)gc * NN;
#pragma unroll
            for (int j = 0; j < 8; j++) {
                int gn = n0 + warp_n * 64 + j * 8 + 2 * cc;
                if (gn < NN)
                    outb[rowoff + gn]     = g * acc[i][j][2 * h]     + xf[rowoff + gn];
                if (gn + 1 < NN)
                    outb[rowoff + gn + 1] = g * acc[i][j][2 * h + 1] + xf[rowoff + gn + 1];
            }
        }
}

// ---------------- launch ----------------
extern "C" void kernel_launch(void* const* d_in, const int* in_sizes, int n_in,
                              void* d_out, int out_size) {
    const float* x     = (const float*)d_in[0];
    const float* fg    = (const float*)d_in[1];
    const float* bg    = (const float*)d_in[2];
    const float* Wq    = (const float*)d_in[3];
    const float* bq    = (const float*)d_in[4];
    const float* Wk    = (const float*)d_in[5];
    const float* bk    = (const float*)d_in[6];
    const float* gamma = (const float*)d_in[7];
    float* out = (float*)d_out;

    pack_kernel<<<(MQK * CH + 255) / 256, 256>>>(Wq, bq, Wk, bk);

    dim3 g1((NN + 127) / 128, MQK / 128, BATCH);
    gemm1_kernel<<<g1, 256>>>(x);

    dim3 g2((NN + 127) / 128, (NN + 127) / 128, BATCH);
    gemm2_kernel<<<g2, 256>>>(fg);

    dim3 g3(CH / 128, (NN + 127) / 128, BATCH);
    gemm3_kernel<<<g3, 256>>>(x, fg, bg, gamma, out);
}

// round 6
// speedup vs baseline: 1.6712x; 1.3753x over previous
#include <cuda_runtime.h>
#include <cuda_bf16.h>
#include <cstdint>
#include <cfloat>

#define BATCH 16
#define CH    512
#define NN    1681
#define CK    256
#define MQK   512
#define EPSV  1e-5f
#define SCALE 0.0625f   /* 256^-0.5 */

// ---------------- scratch ----------------
__device__ uint32_t g_Wp[(CH / 2) * MQK];            // bf16-pair packed weights [kp][m]
__device__ float g_bias[MQK];
__device__ float g_QK[(size_t)BATCH * MQK * NN];     // fp32: Q rows 0..255, K rows 256..511
__device__ float g_P[(size_t)BATCH * NN * NN];       // fp32 sim*scale*fg
__device__ float g_minv[BATCH * NN];
__device__ float g_s1[BATCH * NN];
__device__ float g_s2[BATCH * NN];

// ---------------- helpers ----------------
__device__ __forceinline__ uint32_t packbf(float lo, float hi) {
    __nv_bfloat162 t = __floats2bfloat162_rn(lo, hi);
    return *reinterpret_cast<uint32_t*>(&t);
}

__device__ __forceinline__ void mma_bf16(float c[4], const uint32_t a[4], const uint32_t b[2]) {
    asm volatile(
        "mma.sync.aligned.m16n8k16.row.col.f32.bf16.bf16.f32 "
        "{%0,%1,%2,%3}, {%4,%5,%6,%7}, {%8,%9}, {%0,%1,%2,%3};\n"
        : "+f"(c[0]), "+f"(c[1]), "+f"(c[2]), "+f"(c[3])
        : "r"(a[0]), "r"(a[1]), "r"(a[2]), "r"(a[3]), "r"(b[0]), "r"(b[1]));
}

__device__ __forceinline__ void atomicMinFloat(float* addr, float value) {
    if (value >= 0.f) atomicMin((int*)addr, __float_as_int(value));
    else              atomicMax((unsigned int*)addr, __float_as_uint(value));
}

// ---------------- pack weights (bf16 pairs) + reset stats ----------------
__global__ void pack_kernel(const float* __restrict__ Wq, const float* __restrict__ bq,
                            const float* __restrict__ Wk, const float* __restrict__ bk) {
    int idx = blockIdx.x * blockDim.x + threadIdx.x;
    if (idx < (CH / 2) * MQK) {
        int m = idx & (MQK - 1), kp = idx >> 9;
        float a = (m < CK) ? Wq[m * CH + 2 * kp]     : Wk[(m - CK) * CH + 2 * kp];
        float b = (m < CK) ? Wq[m * CH + 2 * kp + 1] : Wk[(m - CK) * CH + 2 * kp + 1];
        g_Wp[kp * MQK + m] = packbf(a, b);
    }
    if (idx < MQK) g_bias[idx] = (idx < CK) ? bq[idx] : bk[idx - CK];
    if (idx < BATCH * NN) {
        g_minv[idx] = FLT_MAX;
        g_s1[idx] = 0.f;
        g_s2[idx] = 0.f;
    }
}

// fragment compute: tile 128x128, k=32 (16 bf16 pairs), 8 warps (4x2),
// per warp 2x8 m16n8k16
#define FRAG_MMA_LOOP(AS, BS)                                                  \
    _Pragma("unroll")                                                          \
    for (int kk = 0; kk < 2; kk++) {                                           \
        const int kpb = kk * 8;                                                \
        uint32_t af[2][4], bfr[8][2];                                          \
        _Pragma("unroll")                                                      \
        for (int i = 0; i < 2; i++) {                                          \
            int mm = warp_m * 32 + i * 16 + r;                                 \
            af[i][0] = AS[kpb + cc][mm];                                       \
            af[i][1] = AS[kpb + cc][mm + 8];                                   \
            af[i][2] = AS[kpb + cc + 4][mm];                                   \
            af[i][3] = AS[kpb + cc + 4][mm + 8];                               \
        }                                                                      \
        _Pragma("unroll")                                                      \
        for (int j = 0; j < 8; j++) {                                          \
            int nn = warp_n * 64 + j * 8 + r;                                  \
            bfr[j][0] = BS[kpb + cc][nn];                                      \
            bfr[j][1] = BS[kpb + cc + 4][nn];                                  \
        }                                                                      \
        _Pragma("unroll")                                                      \
        for (int i = 0; i < 2; i++)                                            \
            _Pragma("unroll")                                                  \
            for (int j = 0; j < 8; j++) mma_bf16(acc[i][j], af[i], bfr[j]);    \
    }

// =====================================================================
// GEMM1: QK[b][m][n] = Wqk @ xf + bias    M=512, N=1681, K=512 (fp32 out)
// =====================================================================
__global__ __launch_bounds__(256, 2) void gemm1_kernel(const float* __restrict__ x) {
    __shared__ uint32_t As[16][136];
    __shared__ uint32_t Bs[16][136];
    const int b  = blockIdx.z;
    const int m0 = blockIdx.y * 128;
    const int n0 = blockIdx.x * 128;
    const int tid = threadIdx.x;
    const int lane = tid & 31, wid = tid >> 5;
    const int warp_m = wid >> 1, warp_n = wid & 1;
    const int r = lane >> 2, cc = lane & 3;
    const float* xf = x + (size_t)b * CH * NN;

    float acc[2][8][4];
#pragma unroll
    for (int i = 0; i < 2; i++)
#pragma unroll
        for (int j = 0; j < 8; j++)
#pragma unroll
            for (int q = 0; q < 4; q++) acc[i][j][q] = 0.f;

    for (int k0 = 0; k0 < CH; k0 += 32) {
        // A: pre-packed weight pairs, coalesced along m
#pragma unroll
        for (int it = 0; it < 8; it++) {
            int li = tid + it * 256;
            int m = li & 127, kp = li >> 7;
            As[kp][m] = g_Wp[((k0 >> 1) + kp) * MQK + m0 + m];
        }
        // B: xf rows k, k+1 (fp32, coalesced along n), pack to bf16x2
#pragma unroll
        for (int it = 0; it < 8; it++) {
            int li = tid + it * 256;
            int n = li & 127, kp = li >> 7;
            int gn = n0 + n, k = k0 + 2 * kp;
            float f0 = 0.f, f1 = 0.f;
            if (gn < NN) {
                f0 = xf[(size_t)k * NN + gn];
                f1 = xf[(size_t)(k + 1) * NN + gn];
            }
            Bs[kp][n] = packbf(f0, f1);
        }
        __syncthreads();
        FRAG_MMA_LOOP(As, Bs)
        __syncthreads();
    }

    float* outp = g_QK + (size_t)b * MQK * NN;
#pragma unroll
    for (int i = 0; i < 2; i++)
#pragma unroll
        for (int h = 0; h < 2; h++) {
            int m = m0 + warp_m * 32 + i * 16 + r + h * 8;
            float bias = g_bias[m];
#pragma unroll
            for (int j = 0; j < 8; j++) {
                int n = n0 + warp_n * 64 + j * 8 + 2 * cc;
                if (n < NN)     outp[(size_t)m * NN + n]     = acc[i][j][2 * h]     + bias;
                if (n + 1 < NN) outp[(size_t)m * NN + n + 1] = acc[i][j][2 * h + 1] + bias;
            }
        }
}

// =====================================================================
// GEMM2: P[b][n][m] = (Q^T K)*scale*fg (fp32 out) + fused row stats
// =====================================================================
__global__ __launch_bounds__(256, 2) void gemm2_kernel(const float* __restrict__ fg) {
    __shared__ uint32_t As[16][136];
    __shared__ uint32_t Bs[16][136];
    const int b  = blockIdx.z;
    const int n0 = blockIdx.y * 128;
    const int m0 = blockIdx.x * 128;
    const int tid = threadIdx.x;
    const int lane = tid & 31, wid = tid >> 5;
    const int warp_m = wid >> 1, warp_n = wid & 1;
    const int r = lane >> 2, cc = lane & 3;
    const float* Q  = g_QK + (size_t)b * MQK * NN;
    const float* Kp = Q + (size_t)CK * NN;

    float acc[2][8][4];
#pragma unroll
    for (int i = 0; i < 2; i++)
#pragma unroll
        for (int j = 0; j < 8; j++)
#pragma unroll
            for (int q = 0; q < 4; q++) acc[i][j][q] = 0.f;

    for (int k0 = 0; k0 < CK; k0 += 32) {
#pragma unroll
        for (int it = 0; it < 8; it++) {
            int li = tid + it * 256;
            int n = li & 127, kp = li >> 7;
            int gn = n0 + n, k = k0 + 2 * kp;
            float f0 = 0.f, f1 = 0.f;
            if (gn < NN) {
                f0 = Q[(size_t)k * NN + gn];
                f1 = Q[(size_t)(k + 1) * NN + gn];
            }
            As[kp][n] = packbf(f0, f1);
        }
#pragma unroll
        for (int it = 0; it < 8; it++) {
            int li = tid + it * 256;
            int m = li & 127, kp = li >> 7;
            int gm = m0 + m, k = k0 + 2 * kp;
            float f0 = 0.f, f1 = 0.f;
            if (gm < NN) {
                f0 = Kp[(size_t)k * NN + gm];
                f1 = Kp[(size_t)(k + 1) * NN + gm];
            }
            Bs[kp][m] = packbf(f0, f1);
        }
        __syncthreads();
        FRAG_MMA_LOOP(As, Bs)
        __syncthreads();
    }

    const float* FG = fg + (size_t)b * NN * NN;
    float* Pp = g_P + (size_t)b * NN * NN;
#pragma unroll
    for (int i = 0; i < 2; i++)
#pragma unroll
        for (int h = 0; h < 2; h++) {
            int gn = n0 + warp_m * 32 + i * 16 + r + h * 8;
            bool rowvalid = gn < NN;
            size_t rowoff = (size_t)gn * NN;
            float mn = FLT_MAX, s1 = 0.f, s2 = 0.f;
#pragma unroll
            for (int j = 0; j < 8; j++) {
                int gm = m0 + warp_n * 64 + j * 8 + 2 * cc;
                if (rowvalid && gm < NN) {
                    float f = FG[rowoff + gm];
                    float p = acc[i][j][2 * h] * SCALE * f;
                    Pp[rowoff + gm] = p;
                    mn = fminf(mn, p); s1 += p * f; s2 += f;
                }
                if (rowvalid && gm + 1 < NN) {
                    float f = FG[rowoff + gm + 1];
                    float p = acc[i][j][2 * h + 1] * SCALE * f;
                    Pp[rowoff + gm + 1] = p;
                    mn = fminf(mn, p); s1 += p * f; s2 += f;
                }
            }
            mn = fminf(mn, __shfl_xor_sync(0xffffffffu, mn, 1));
            mn = fminf(mn, __shfl_xor_sync(0xffffffffu, mn, 2));
            s1 += __shfl_xor_sync(0xffffffffu, s1, 1);
            s1 += __shfl_xor_sync(0xffffffffu, s1, 2);
            s2 += __shfl_xor_sync(0xffffffffu, s2, 1);
            s2 += __shfl_xor_sync(0xffffffffu, s2, 2);
            if (cc == 0 && rowvalid) {
                atomicMinFloat(&g_minv[b * NN + gn], mn);
                atomicAdd(&g_s1[b * NN + gn], s1);
                atomicAdd(&g_s2[b * NN + gn], s2);
            }
        }
}

// =====================================================================
// GEMM3 (transposed): out[c][n] = gamma * sum_m xf[c][m]*sim_f[n][m] + x[c][n]
// M = c (512), N = n (1681), K = m (1681); sim on the fly; inv fused.
// =====================================================================
__global__ __launch_bounds__(256, 2) void gemm3_kernel(const float* __restrict__ x,
                                                       const float* __restrict__ fg,
                                                       const float* __restrict__ bg,
                                                       const float* __restrict__ gamma,
                                                       float* __restrict__ out) {
    __shared__ uint32_t As[16][136];
    __shared__ uint32_t Bs[16][136];
    __shared__ float rMin[128], rInv[128];
    const int b  = blockIdx.z;
    const int c0 = blockIdx.x * 128;
    const int n0 = blockIdx.y * 128;
    const int tid = threadIdx.x;
    const int lane = tid & 31, wid = tid >> 5;
    const int warp_m = wid >> 1, warp_n = wid & 1;
    const int r = lane >> 2, cc = lane & 3;

    if (tid < 128) {
        int n = n0 + tid;
        if (n < NN) {
            float mn = g_minv[b * NN + n];
            rMin[tid] = mn;
            rInv[tid] = 1.f / (g_s1[b * NN + n] - mn * g_s2[b * NN + n] + EPSV);
        } else {
            rMin[tid] = 0.f;
            rInv[tid] = 0.f;
        }
    }
    __syncthreads();

    const float* P  = g_P + (size_t)b * NN * NN;
    const float* FG = fg + (size_t)b * NN * NN;
    const float* BG = bg + (size_t)b * NN * NN;
    const float* xf = x + (size_t)b * CH * NN;

    float acc[2][8][4];
#pragma unroll
    for (int i = 0; i < 2; i++)
#pragma unroll
        for (int j = 0; j < 8; j++)
#pragma unroll
            for (int q = 0; q < 4; q++) acc[i][j][q] = 0.f;

    for (int m0 = 0; m0 < NN; m0 += 32) {
        // A: xf[c][m] pairs along m (each lane: 8B contiguous; group: 128B)
#pragma unroll
        for (int it = 0; it < 8; it++) {
            int li = tid + it * 256;
            int mp = li & 15, c = li >> 4;
            int gm = m0 + 2 * mp, gc = c0 + c;
            float f0 = 0.f, f1 = 0.f;
            if (gm < NN)     f0 = xf[(size_t)gc * NN + gm];
            if (gm + 1 < NN) f1 = xf[(size_t)gc * NN + gm + 1];
            As[mp][c] = packbf(f0, f1);
        }
        // B: sim_final[n][m] pairs along m, on the fly
#pragma unroll
        for (int it = 0; it < 8; it++) {
            int li = tid + it * 256;
            int mp = li & 15, nl = li >> 4;
            int gm = m0 + 2 * mp, gn = n0 + nl;
            float v0 = 0.f, v1 = 0.f;
            if (gn < NN) {
                float mnv = rMin[nl], inv = rInv[nl];
                size_t a = (size_t)gn * NN + gm;
                if (gm < NN)     v0 = (P[a]     - mnv) * FG[a]     * inv + BG[a];
                if (gm + 1 < NN) v1 = (P[a + 1] - mnv) * FG[a + 1] * inv + BG[a + 1];
            }
            Bs[mp][nl] = packbf(v0, v1);
        }
        __syncthreads();
        FRAG_MMA_LOOP(As, Bs)
        __syncthreads();
    }

    const float g = gamma[0];
    float* outb = out + (size_t)b * CH * NN;
#pragma unroll
    for (int i = 0; i < 2; i++)
#pragma unroll
        for (int h = 0; h < 2; h++) {
            int gc = c0 + warp_m * 32 + i * 16 + r + h * 8;
            size_t rowoff = (size_t)gc * NN;
#pragma unroll
            for (int j = 0; j < 8; j++) {
                int gn = n0 + warp_n * 64 + j * 8 + 2 * cc;
                if (gn < NN)
                    outb[rowoff + gn]     = g * acc[i][j][2 * h]     + xf[rowoff + gn];
                if (gn + 1 < NN)
                    outb[rowoff + gn + 1] = g * acc[i][j][2 * h + 1] + xf[rowoff + gn + 1];
            }
        }
}

// ---------------- launch ----------------
extern "C" void kernel_launch(void* const* d_in, const int* in_sizes, int n_in,
                              void* d_out, int out_size) {
    const float* x     = (const float*)d_in[0];
    const float* fg    = (const float*)d_in[1];
    const float* bg    = (const float*)d_in[2];
    const float* Wq    = (const float*)d_in[3];
    const float* bq    = (const float*)d_in[4];
    const float* Wk    = (const float*)d_in[5];
    const float* bk    = (const float*)d_in[6];
    const float* gamma = (const float*)d_in[7];
    float* out = (float*)d_out;

    pack_kernel<<<((CH / 2) * MQK + 255) / 256, 256>>>(Wq, bq, Wk, bk);

    dim3 g1((NN + 127) / 128, MQK / 128, BATCH);
    gemm1_kernel<<<g1, 256>>>(x);

    dim3 g2((NN + 127) / 128, (NN + 127) / 128, BATCH);
    gemm2_kernel<<<g2, 256>>>(fg);

    dim3 g3(CH / 128, (NN + 127) / 128, BATCH);
    gemm3_kernel<<<g3, 256>>>(x, fg, bg, gamma, out);
}

// round 9
// speedup vs baseline: 3.6688x; 2.1953x over previous
#include <cuda_runtime.h>
#include <cuda_bf16.h>
#include <cstdint>
#include <cfloat>

#define BATCH 16
#define CH    512
#define NN    1681
#define CK    256
#define MQK   512
#define NPADC 1792            /* padded n columns (16B-aligned rows, covers 14*128) */
#define NPP   896             /* pair rows for 1792 */
#define EPSV  1e-5f
#define SCALE 0.0625f         /* 256^-0.5 */

// ---------------- scratch (all uint32 = packed bf16x2 unless noted) ----------------
__device__ uint32_t g_Wp[(CH / 2) * MQK];                       // [kp][m] pairs along C
__device__ float    g_bias[MQK];
__device__ uint32_t g_xk[(size_t)BATCH * (CH / 2) * NPADC];     // [b][kp][n] pairs along C
__device__ uint32_t g_xvT[(size_t)BATCH * NPP * CH];            // [b][mp][c] pairs along N
__device__ uint32_t g_QKp[(size_t)BATCH * 256 * NPADC];         // [b][pg][n]; Q pg<128, K pg>=128
__device__ uint32_t g_P[(size_t)BATCH * NN * NPP];              // [b][n][mp] bf16-pair P
__device__ uint32_t g_simfT[(size_t)BATCH * NPP * NPADC];       // [b][mp][n] bf16-pair sim_final^T
__device__ float    g_minv[BATCH * NN];
__device__ float    g_s1[BATCH * NN];
__device__ float    g_s2[BATCH * NN];

// ---------------- helpers ----------------
__device__ __forceinline__ uint32_t packbf(float lo, float hi) {
    __nv_bfloat162 t = __floats2bfloat162_rn(lo, hi);
    return *reinterpret_cast<uint32_t*>(&t);
}
__device__ __forceinline__ float2 unpackbf(uint32_t u) {
    __nv_bfloat162 t = *reinterpret_cast<__nv_bfloat162*>(&u);
    return make_float2(__bfloat162float(t.x), __bfloat162float(t.y));
}
__device__ __forceinline__ void mma_bf16(float c[4], const uint32_t a[4], const uint32_t b[2]) {
    asm volatile(
        "mma.sync.aligned.m16n8k16.row.col.f32.bf16.bf16.f32 "
        "{%0,%1,%2,%3}, {%4,%5,%6,%7}, {%8,%9}, {%0,%1,%2,%3};\n"
        : "+f"(c[0]), "+f"(c[1]), "+f"(c[2]), "+f"(c[3])
        : "r"(a[0]), "r"(a[1]), "r"(a[2]), "r"(a[3]), "r"(b[0]), "r"(b[1]));
}
__device__ __forceinline__ void atomicMinFloat(float* addr, float value) {
    if (value >= 0.f) atomicMin((int*)addr, __float_as_int(value));
    else              atomicMax((unsigned int*)addr, __float_as_uint(value));
}
__device__ __forceinline__ void cpa16(void* s, const uint32_t* g) {
    uint32_t sa = (uint32_t)__cvta_generic_to_shared(s);
    asm volatile("cp.async.cg.shared.global [%0], [%1], 16;" :: "r"(sa), "l"(g));
}
#define CP_COMMIT() asm volatile("cp.async.commit_group;")
#define CP_WAIT1()  asm volatile("cp.async.wait_group 1;")
#define CP_WAIT0()  asm volatile("cp.async.wait_group 0;")

// issue one 16-row x 128-col uint32 tile per operand (2x cp.async 16B per thread each)
#define ISSUE_TILE(DA, DB, SA, STA, SB, STB)                                   \
    _Pragma("unroll")                                                          \
    for (int it = 0; it < 2; it++) {                                           \
        int li = threadIdx.x + it * 256;                                       \
        int row = li >> 5, c4 = (li & 31) * 4;                                 \
        cpa16(&DA[row][c4], (SA) + (size_t)row * (STA) + c4);                  \
        cpa16(&DB[row][c4], (SB) + (size_t)row * (STB) + c4);                  \
    }

// fragment compute: tile 128x128, k=32 (16 pair rows), 8 warps (4x2), 2x8 m16n8k16
#define FRAG_MMA_LOOP(AS, BS)                                                  \
    _Pragma("unroll")                                                          \
    for (int kk = 0; kk < 2; kk++) {                                           \
        const int kpb = kk * 8;                                                \
        uint32_t af[2][4], bfr[8][2];                                          \
        _Pragma("unroll")                                                      \
        for (int i = 0; i < 2; i++) {                                          \
            int mm = warp_m * 32 + i * 16 + r;                                 \
            af[i][0] = AS[kpb + cc][mm];                                       \
            af[i][1] = AS[kpb + cc][mm + 8];                                   \
            af[i][2] = AS[kpb + cc + 4][mm];                                   \
            af[i][3] = AS[kpb + cc + 4][mm + 8];                               \
        }                                                                      \
        _Pragma("unroll")                                                      \
        for (int j = 0; j < 8; j++) {                                          \
            int nn2 = warp_n * 64 + j * 8 + r;                                 \
            bfr[j][0] = BS[kpb + cc][nn2];                                     \
            bfr[j][1] = BS[kpb + cc + 4][nn2];                                 \
        }                                                                      \
        _Pragma("unroll")                                                      \
        for (int i = 0; i < 2; i++)                                            \
            _Pragma("unroll")                                                  \
            for (int j = 0; j < 8; j++) mma_bf16(acc[i][j], af[i], bfr[j]);    \
    }

#define ACC_INIT()                                                             \
    float acc[2][8][4];                                                        \
    _Pragma("unroll")                                                          \
    for (int i = 0; i < 2; i++)                                                \
        _Pragma("unroll")                                                      \
        for (int j = 0; j < 8; j++)                                            \
            _Pragma("unroll")                                                  \
            for (int q = 0; q < 4; q++) acc[i][j][q] = 0.f;

#define WARP_VARS()                                                            \
    const int tid = threadIdx.x;                                               \
    const int lane = tid & 31, wid = tid >> 5;                                 \
    const int warp_m = wid >> 1, warp_n = wid & 1;                             \
    const int r = lane >> 2, cc = lane & 3;

// ---------------- pack: weights + bias + stats reset ----------------
__global__ void pack_misc_kernel(const float* __restrict__ Wq, const float* __restrict__ bq,
                                 const float* __restrict__ Wk, const float* __restrict__ bk) {
    int idx = blockIdx.x * blockDim.x + threadIdx.x;
    if (idx < (CH / 2) * MQK) {
        int m = idx & (MQK - 1), kp = idx >> 9;
        float a = (m < CK) ? Wq[m * CH + 2 * kp]     : Wk[(m - CK) * CH + 2 * kp];
        float b = (m < CK) ? Wq[m * CH + 2 * kp + 1] : Wk[(m - CK) * CH + 2 * kp + 1];
        g_Wp[kp * MQK + m] = packbf(a, b);
    }
    if (idx < MQK) g_bias[idx] = (idx < CK) ? bq[idx] : bk[idx - CK];
    if (idx < BATCH * NN) {
        g_minv[idx] = FLT_MAX;
        g_s1[idx] = 0.f;
        g_s2[idx] = 0.f;
    }
}

// ---------------- pack: x -> pairs along C, [b][kp][n] ----------------
__global__ void pack_xk_kernel(const float* __restrict__ x) {
    int n = blockIdx.x * 256 + threadIdx.x;   // grid.x = 7 -> 1792
    int kp = blockIdx.y;                      // 0..255
    int b  = blockIdx.z;
    uint32_t v = 0;
    if (n < NN) {
        const float* xb = x + (size_t)b * CH * NN;
        v = packbf(xb[(size_t)(2 * kp) * NN + n], xb[(size_t)(2 * kp + 1) * NN + n]);
    }
    g_xk[((size_t)b * (CH / 2) + kp) * NPADC + n] = v;
}

// ---------------- pack: x -> transposed pairs along N, [b][mp][c] ----------------
__global__ void pack_xvT_kernel(const float* __restrict__ x) {
    __shared__ uint32_t T[32][33];
    int mp0 = blockIdx.x * 32;                // 27 tiles -> 864 rows
    int c0  = blockIdx.y * 32;                // 16 tiles -> 512
    int b   = blockIdx.z;
    int tx = threadIdx.x, ty = threadIdx.y;   // (32, 8)
    const float* xb = x + (size_t)b * CH * NN;
#pragma unroll
    for (int p = 0; p < 4; p++) {
        int c = c0 + p * 8 + ty;
        int m = 2 * (mp0 + tx);
        float f0 = 0.f, f1 = 0.f;
        if (m < NN)     f0 = xb[(size_t)c * NN + m];
        if (m + 1 < NN) f1 = xb[(size_t)c * NN + m + 1];
        T[tx][p * 8 + ty] = packbf(f0, f1);
    }
    __syncthreads();
#pragma unroll
    for (int p = 0; p < 4; p++) {
        int row = p * 8 + ty;                 // mp-local
        g_xvT[((size_t)b * NPP + mp0 + row) * CH + c0 + tx] = T[row][tx];
    }
}

// =====================================================================
// GEMM1: QK = Wqk @ xf + bias -> bf16 (m, m+8)-pairs  [b][pg][n]
// =====================================================================
__global__ __launch_bounds__(256, 2) void gemm1_kernel() {
    __shared__ uint32_t As[2][16][136];
    __shared__ uint32_t Bs[2][16][136];
    const int b  = blockIdx.z;
    const int m0 = blockIdx.y * 128;
    const int n0 = blockIdx.x * 128;
    WARP_VARS();
    ACC_INIT();

    const uint32_t* srcA0 = g_Wp + (size_t)0 * MQK + m0;
    const uint32_t* srcB0 = g_xk + (size_t)b * (CH / 2) * NPADC + n0;
    const int NSTEP = CH / 32;  // 16

    ISSUE_TILE(As[0], Bs[0], srcA0, MQK, srcB0, NPADC);
    CP_COMMIT();
    for (int s = 0; s < NSTEP; s++) {
        int buf = s & 1;
        if (s + 1 < NSTEP) {
            const uint32_t* sa = srcA0 + (size_t)(s + 1) * 16 * MQK;
            const uint32_t* sb = srcB0 + (size_t)(s + 1) * 16 * NPADC;
            ISSUE_TILE(As[buf ^ 1], Bs[buf ^ 1], sa, MQK, sb, NPADC);
            CP_COMMIT();
            CP_WAIT1();
        } else {
            CP_WAIT0();
        }
        __syncthreads();
        FRAG_MMA_LOOP(As[buf], Bs[buf])
        __syncthreads();
    }

    uint32_t* outp = g_QKp + (size_t)b * 256 * NPADC;
#pragma unroll
    for (int i = 0; i < 2; i++) {
        int m_lo = m0 + warp_m * 32 + i * 16 + r;       // (m&15)==r<8
        int pg = (m_lo >> 4) * 8 + r;
        float b_lo = g_bias[m_lo], b_hi = g_bias[m_lo + 8];
#pragma unroll
        for (int j = 0; j < 8; j++) {
            int n = n0 + warp_n * 64 + j * 8 + 2 * cc;
            uint2 u;
            u.x = packbf(acc[i][j][0] + b_lo, acc[i][j][2] + b_hi);
            u.y = packbf(acc[i][j][1] + b_lo, acc[i][j][3] + b_hi);
            *reinterpret_cast<uint2*>(&outp[(size_t)pg * NPADC + n]) = u;
        }
    }
}

// =====================================================================
// GEMM2: P = (Q^T K)*scale*fg -> bf16 pairs [b][n][mp] + fused row stats
// =====================================================================
__global__ __launch_bounds__(256, 2) void gemm2_kernel(const float* __restrict__ fg) {
    __shared__ uint32_t As[2][16][136];
    __shared__ uint32_t Bs[2][16][136];
    const int b  = blockIdx.z;
    const int n0 = blockIdx.y * 128;
    const int m0 = blockIdx.x * 128;
    WARP_VARS();
    ACC_INIT();

    const uint32_t* srcA0 = g_QKp + (size_t)b * 256 * NPADC + n0;                   // Q pair rows 0..127
    const uint32_t* srcB0 = g_QKp + ((size_t)b * 256 + 128) * NPADC + m0;           // K pair rows
    const int NSTEP = CK / 32;  // 8

    ISSUE_TILE(As[0], Bs[0], srcA0, NPADC, srcB0, NPADC);
    CP_COMMIT();
    for (int s = 0; s < NSTEP; s++) {
        int buf = s & 1;
        if (s + 1 < NSTEP) {
            const uint32_t* sa = srcA0 + (size_t)(s + 1) * 16 * NPADC;
            const uint32_t* sb = srcB0 + (size_t)(s + 1) * 16 * NPADC;
            ISSUE_TILE(As[buf ^ 1], Bs[buf ^ 1], sa, NPADC, sb, NPADC);
            CP_COMMIT();
            CP_WAIT1();
        } else {
            CP_WAIT0();
        }
        __syncthreads();
        FRAG_MMA_LOOP(As[buf], Bs[buf])
        __syncthreads();
    }

    const float* FG = fg + (size_t)b * NN * NN;
    uint32_t* Pp = g_P + (size_t)b * NN * NPP;
#pragma unroll
    for (int i = 0; i < 2; i++)
#pragma unroll
        for (int h = 0; h < 2; h++) {
            int gn = n0 + warp_m * 32 + i * 16 + r + h * 8;
            bool rowvalid = gn < NN;
            size_t rowoff = (size_t)gn * NN;
            float mn = FLT_MAX, s1 = 0.f, s2 = 0.f;
#pragma unroll
            for (int j = 0; j < 8; j++) {
                int gm = m0 + warp_n * 64 + j * 8 + 2 * cc;
                if (rowvalid && gm < NN) {
                    float f0 = FG[rowoff + gm];
                    float p0 = acc[i][j][2 * h] * SCALE * f0;
                    mn = fminf(mn, p0); s1 += p0 * f0; s2 += f0;
                    float p1 = 0.f;
                    if (gm + 1 < NN) {
                        float f1 = FG[rowoff + gm + 1];
                        p1 = acc[i][j][2 * h + 1] * SCALE * f1;
                        mn = fminf(mn, p1); s1 += p1 * f1; s2 += f1;
                    }
                    Pp[(size_t)gn * NPP + (gm >> 1)] = packbf(p0, p1);
                }
            }
            mn = fminf(mn, __shfl_xor_sync(0xffffffffu, mn, 1));
            mn = fminf(mn, __shfl_xor_sync(0xffffffffu, mn, 2));
            s1 += __shfl_xor_sync(0xffffffffu, s1, 1);
            s1 += __shfl_xor_sync(0xffffffffu, s1, 2);
            s2 += __shfl_xor_sync(0xffffffffu, s2, 1);
            s2 += __shfl_xor_sync(0xffffffffu, s2, 2);
            if (cc == 0 && rowvalid) {
                atomicMinFloat(&g_minv[b * NN + gn], mn);
                atomicAdd(&g_s1[b * NN + gn], s1);
                atomicAdd(&g_s2[b * NN + gn], s2);
            }
        }
}

// =====================================================================
// simf: sim_final = (P - min)*fg*inv + bg -> bf16 pairs TRANSPOSED [b][mp][n]
// =====================================================================
__global__ void simf_kernel(const float* __restrict__ fg, const float* __restrict__ bg) {
    __shared__ uint32_t T[32][33];
    __shared__ float sMin[32], sInv[32];
    const int mp0 = blockIdx.x * 32;          // 27 tiles
    const int n0  = blockIdx.y * 32;          // 53 tiles -> 1696
    const int b   = blockIdx.z;
    const int tx = threadIdx.x, ty = threadIdx.y;
    const int tid = ty * 32 + tx;

    if (tid < 32) {
        int n = n0 + tid;
        if (n < NN) {
            float mn = g_minv[b * NN + n];
            sMin[tid] = mn;
            sInv[tid] = 1.f / (g_s1[b * NN + n] - mn * g_s2[b * NN + n] + EPSV);
        } else {
            sMin[tid] = 0.f; sInv[tid] = 0.f;
        }
    }
    __syncthreads();

    const float* FG = fg + (size_t)b * NN * NN;
    const float* BG = bg + (size_t)b * NN * NN;
    const uint32_t* Pp = g_P + (size_t)b * NN * NPP;
#pragma unroll
    for (int p = 0; p < 4; p++) {
        int ny = p * 8 + ty;
        int n = n0 + ny;
        int mp = mp0 + tx, m = 2 * mp;
        float v0 = 0.f, v1 = 0.f;
        if (n < NN && m < NN) {
            float2 pv = unpackbf(Pp[(size_t)n * NPP + mp]);
            size_t a = (size_t)n * NN + m;
            float mn = sMin[ny], inv = sInv[ny];
            v0 = (pv.x - mn) * FG[a] * inv + BG[a];
            if (m + 1 < NN)
                v1 = (pv.y - mn) * FG[a + 1] * inv + BG[a + 1];
        }
        T[tx][ny] = packbf(v0, v1);
    }
    __syncthreads();
#pragma unroll
    for (int p = 0; p < 4; p++) {
        int row = p * 8 + ty;                 // mp-local
        g_simfT[((size_t)b * NPP + mp0 + row) * NPADC + n0 + tx] = T[row][tx];
    }
}

// =====================================================================
// GEMM3 (transposed): out[c][n] = gamma * sum_m V_pair @ simf_T + x[c][n]
// =====================================================================
__global__ __launch_bounds__(256, 2) void gemm3_kernel(const float* __restrict__ x,
                                                       const float* __restrict__ gamma,
                                                       float* __restrict__ out) {
    __shared__ uint32_t As[2][16][136];
    __shared__ uint32_t Bs[2][16][136];
    const int b  = blockIdx.z;
    const int c0 = blockIdx.x * 128;
    const int n0 = blockIdx.y * 128;
    WARP_VARS();
    ACC_INIT();

    const uint32_t* srcA0 = g_xvT   + (size_t)b * NPP * CH + c0;
    const uint32_t* srcB0 = g_simfT + (size_t)b * NPP * NPADC + n0;
    const int NSTEP = 53;   // 53*16 = 848 pair rows >= ceil(1681/2)

    ISSUE_TILE(As[0], Bs[0], srcA0, CH, srcB0, NPADC);
    CP_COMMIT();
    for (int s = 0; s < NSTEP; s++) {
        int buf = s & 1;
        if (s + 1 < NSTEP) {
            const uint32_t* sa = srcA0 + (size_t)(s + 1) * 16 * CH;
            const uint32_t* sb = srcB0 + (size_t)(s + 1) * 16 * NPADC;
            ISSUE_TILE(As[buf ^ 1], Bs[buf ^ 1], sa, CH, sb, NPADC);
            CP_COMMIT();
            CP_WAIT1();
        } else {
            CP_WAIT0();
        }
        __syncthreads();
        FRAG_MMA_LOOP(As[buf], Bs[buf])
        __syncthreads();
    }

    const float g = gamma[0];
    const float* xf = x + (size_t)b * CH * NN;
    float* outb = out + (size_t)b * CH * NN;
#pragma unroll
    for (int i = 0; i < 2; i++)
#pragma unroll
        for (int h = 0; h < 2; h++) {
            int gc = c0 + warp_m * 32 + i * 16 + r + h * 8;
            size_t rowoff = (size_t)gc * NN;
#pragma unroll
            for (int j = 0; j < 8; j++) {
                int gn = n0 + warp_n * 64 + j * 8 + 2 * cc;
                if (gn < NN)
                    outb[rowoff + gn]     = g * acc[i][j][2 * h]     + xf[rowoff + gn];
                if (gn + 1 < NN)
                    outb[rowoff + gn + 1] = g * acc[i][j][2 * h + 1] + xf[rowoff + gn + 1];
            }
        }
}

// ---------------- launch ----------------
extern "C" void kernel_launch(void* const* d_in, const int* in_sizes, int n_in,
                              void* d_out, int out_size) {
    const float* x     = (const float*)d_in[0];
    const float* fg    = (const float*)d_in[1];
    const float* bg    = (const float*)d_in[2];
    const float* Wq    = (const float*)d_in[3];
    const float* bq    = (const float*)d_in[4];
    const float* Wk    = (const float*)d_in[5];
    const float* bk    = (const float*)d_in[6];
    const float* gamma = (const float*)d_in[7];
    float* out = (float*)d_out;

    pack_misc_kernel<<<((CH / 2) * MQK + 255) / 256, 256>>>(Wq, bq, Wk, bk);
    pack_xk_kernel<<<dim3(7, CH / 2, BATCH), 256>>>(x);
    pack_xvT_kernel<<<dim3(27, 16, BATCH), dim3(32, 8)>>>(x);

    gemm1_kernel<<<dim3(14, 4, BATCH), 256>>>();
    gemm2_kernel<<<dim3(14, 14, BATCH), 256>>>(fg);
    simf_kernel<<<dim3(27, 53, BATCH), dim3(32, 8)>>>(fg, bg);
    gemm3_kernel<<<dim3(4, 14, BATCH), 256>>>(x, gamma, out);
}

// round 10
// speedup vs baseline: 4.8429x; 1.3200x over previous
#include <cuda_runtime.h>
#include <cuda_bf16.h>
#include <cstdint>
#include <cfloat>

#define BATCH 16
#define CH    512
#define NN    1681
#define CK    256
#define MQK   512
#define NPADC 1792            /* padded n columns (16B-aligned rows, covers 14*128) */
#define NPP   896             /* pair rows for 1792 */
#define EPSV  1e-5f
#define SCALE 0.0625f         /* 256^-0.5 */

// ---------------- scratch (all uint32 = packed bf16x2 unless noted) ----------------
__device__ uint32_t g_Wp[(CH / 2) * MQK];                       // [kp][m] pairs along C
__device__ float    g_bias[MQK];
__device__ uint32_t g_xk[(size_t)BATCH * (CH / 2) * NPADC];     // [b][kp][n] pairs along C
__device__ uint32_t g_xvT[(size_t)BATCH * NPP * CH];            // [b][mp][c] pairs along N
__device__ uint32_t g_QKp[(size_t)BATCH * 256 * NPADC];         // [b][pg][n]; Q pg<128, K pg>=128
__device__ uint32_t g_P[(size_t)BATCH * NN * NPP];              // [b][n][mp] bf16-pair P
__device__ uint32_t g_simfT[(size_t)BATCH * NPP * NPADC];       // [b][mp][n] bf16-pair sim_final^T
__device__ float    g_minv[BATCH * NN];
__device__ float    g_s1[BATCH * NN];
__device__ float    g_s2[BATCH * NN];

// ---------------- helpers ----------------
__device__ __forceinline__ uint32_t packbf(float lo, float hi) {
    __nv_bfloat162 t = __floats2bfloat162_rn(lo, hi);
    return *reinterpret_cast<uint32_t*>(&t);
}
__device__ __forceinline__ float2 unpackbf(uint32_t u) {
    __nv_bfloat162 t = *reinterpret_cast<__nv_bfloat162*>(&u);
    return make_float2(__bfloat162float(t.x), __bfloat162float(t.y));
}
__device__ __forceinline__ void mma_bf16(float c[4], const uint32_t a[4], const uint32_t b[2]) {
    asm volatile(
        "mma.sync.aligned.m16n8k16.row.col.f32.bf16.bf16.f32 "
        "{%0,%1,%2,%3}, {%4,%5,%6,%7}, {%8,%9}, {%0,%1,%2,%3};\n"
        : "+f"(c[0]), "+f"(c[1]), "+f"(c[2]), "+f"(c[3])
        : "r"(a[0]), "r"(a[1]), "r"(a[2]), "r"(a[3]), "r"(b[0]), "r"(b[1]));
}
__device__ __forceinline__ void atomicMinFloat(float* addr, float value) {
    if (value >= 0.f) atomicMin((int*)addr, __float_as_int(value));
    else              atomicMax((unsigned int*)addr, __float_as_uint(value));
}
__device__ __forceinline__ void cpa16(void* s, const uint32_t* g) {
    uint32_t sa = (uint32_t)__cvta_generic_to_shared(s);
    asm volatile("cp.async.cg.shared.global [%0], [%1], 16;" :: "r"(sa), "l"(g));
}
#define CP_COMMIT() asm volatile("cp.async.commit_group;")
#define CP_WAIT0()  asm volatile("cp.async.wait_group 0;")

// issue one 16-row x 128-col uint32 tile per operand (2x cp.async 16B per thread each)
#define ISSUE_TILE(DA, DB, SA, STA, SB, STB)                                   \
    _Pragma("unroll")                                                          \
    for (int it = 0; it < 2; it++) {                                           \
        int li = threadIdx.x + it * 256;                                       \
        int row = li >> 5, c4 = (li & 31) * 4;                                 \
        cpa16(&DA[row][c4], (SA) + (size_t)row * (STA) + c4);                  \
        cpa16(&DB[row][c4], (SB) + (size_t)row * (STB) + c4);                  \
    }

// canonical single-sync 2-stage pipeline over NSTEP k-chunks
#define PIPE_LOOP(NSTEP, STA, STB)                                             \
    ISSUE_TILE(As[0], Bs[0], srcA0, (STA), srcB0, (STB));                      \
    CP_COMMIT();                                                               \
    for (int s = 0; s < (NSTEP); s++) {                                        \
        int buf = s & 1;                                                       \
        CP_WAIT0();                                                            \
        __syncthreads();                                                       \
        if (s + 1 < (NSTEP)) {                                                 \
            const uint32_t* sa_ = srcA0 + (size_t)(s + 1) * 16 * (STA);        \
            const uint32_t* sb_ = srcB0 + (size_t)(s + 1) * 16 * (STB);        \
            ISSUE_TILE(As[buf ^ 1], Bs[buf ^ 1], sa_, (STA), sb_, (STB));      \
            CP_COMMIT();                                                       \
        }                                                                      \
        FRAG_MMA_LOOP(As[buf], Bs[buf])                                        \
    }

// fragment compute: tile 128x128, k=32 (16 pair rows), 8 warps (4x2), 2x8 m16n8k16
#define FRAG_MMA_LOOP(AS, BS)                                                  \
    _Pragma("unroll")                                                          \
    for (int kk = 0; kk < 2; kk++) {                                           \
        const int kpb = kk * 8;                                                \
        uint32_t af[2][4], bfr[8][2];                                          \
        _Pragma("unroll")                                                      \
        for (int i = 0; i < 2; i++) {                                          \
            int mm = warp_m * 32 + i * 16 + r;                                 \
            af[i][0] = AS[kpb + cc][mm];                                       \
            af[i][1] = AS[kpb + cc][mm + 8];                                   \
            af[i][2] = AS[kpb + cc + 4][mm];                                   \
            af[i][3] = AS[kpb + cc + 4][mm + 8];                               \
        }                                                                      \
        _Pragma("unroll")                                                      \
        for (int j = 0; j < 8; j++) {                                          \
            int nn2 = warp_n * 64 + j * 8 + r;                                 \
            bfr[j][0] = BS[kpb + cc][nn2];                                     \
            bfr[j][1] = BS[kpb + cc + 4][nn2];                                 \
        }                                                                      \
        _Pragma("unroll")                                                      \
        for (int i = 0; i < 2; i++)                                            \
            _Pragma("unroll")                                                  \
            for (int j = 0; j < 8; j++) mma_bf16(acc[i][j], af[i], bfr[j]);    \
    }

#define ACC_INIT()                                                             \
    float acc[2][8][4];                                                        \
    _Pragma("unroll")                                                          \
    for (int i = 0; i < 2; i++)                                                \
        _Pragma("unroll")                                                      \
        for (int j = 0; j < 8; j++)                                            \
            _Pragma("unroll")                                                  \
            for (int q = 0; q < 4; q++) acc[i][j][q] = 0.f;

#define WARP_VARS()                                                            \
    const int tid = threadIdx.x;                                               \
    const int lane = tid & 31, wid = tid >> 5;                                 \
    const int warp_m = wid >> 1, warp_n = wid & 1;                             \
    const int r = lane >> 2, cc = lane & 3;

// ---------------- pack: weights + bias + stats reset ----------------
__global__ void pack_misc_kernel(const float* __restrict__ Wq, const float* __restrict__ bq,
                                 const float* __restrict__ Wk, const float* __restrict__ bk) {
    int idx = blockIdx.x * blockDim.x + threadIdx.x;
    if (idx < (CH / 2) * MQK) {
        int m = idx & (MQK - 1), kp = idx >> 9;
        float a = (m < CK) ? Wq[m * CH + 2 * kp]     : Wk[(m - CK) * CH + 2 * kp];
        float b = (m < CK) ? Wq[m * CH + 2 * kp + 1] : Wk[(m - CK) * CH + 2 * kp + 1];
        g_Wp[kp * MQK + m] = packbf(a, b);
    }
    if (idx < MQK) g_bias[idx] = (idx < CK) ? bq[idx] : bk[idx - CK];
    if (idx < BATCH * NN) {
        g_minv[idx] = FLT_MAX;
        g_s1[idx] = 0.f;
        g_s2[idx] = 0.f;
    }
}

// ---------------- pack: x -> pairs along C, [b][kp][n] ----------------
__global__ void pack_xk_kernel(const float* __restrict__ x) {
    int n = blockIdx.x * 256 + threadIdx.x;   // grid.x = 7 -> 1792
    int kp = blockIdx.y;                      // 0..255
    int b  = blockIdx.z;
    uint32_t v = 0;
    if (n < NN) {
        const float* xb = x + (size_t)b * CH * NN;
        v = packbf(xb[(size_t)(2 * kp) * NN + n], xb[(size_t)(2 * kp + 1) * NN + n]);
    }
    g_xk[((size_t)b * (CH / 2) + kp) * NPADC + n] = v;
}

// ---------------- pack: x -> transposed pairs along N, [b][mp][c] ----------------
__global__ void pack_xvT_kernel(const float* __restrict__ x) {
    __shared__ uint32_t T[32][33];
    int mp0 = blockIdx.x * 32;                // 27 tiles -> 864 rows
    int c0  = blockIdx.y * 32;                // 16 tiles -> 512
    int b   = blockIdx.z;
    int tx = threadIdx.x, ty = threadIdx.y;   // (32, 8)
    const float* xb = x + (size_t)b * CH * NN;
#pragma unroll
    for (int p = 0; p < 4; p++) {
        int c = c0 + p * 8 + ty;
        int m = 2 * (mp0 + tx);
        float f0 = 0.f, f1 = 0.f;
        if (m < NN)     f0 = xb[(size_t)c * NN + m];
        if (m + 1 < NN) f1 = xb[(size_t)c * NN + m + 1];
        T[tx][p * 8 + ty] = packbf(f0, f1);
    }
    __syncthreads();
#pragma unroll
    for (int p = 0; p < 4; p++) {
        int row = p * 8 + ty;                 // mp-local
        g_xvT[((size_t)b * NPP + mp0 + row) * CH + c0 + tx] = T[row][tx];
    }
}

// =====================================================================
// GEMM1: QK = Wqk @ xf + bias -> bf16 (m, m+8)-pairs  [b][pg][n]
// =====================================================================
__global__ __launch_bounds__(256, 2) void gemm1_kernel() {
    __shared__ uint32_t As[2][16][136];
    __shared__ uint32_t Bs[2][16][136];
    const int b  = blockIdx.z;
    const int m0 = blockIdx.y * 128;
    const int n0 = blockIdx.x * 128;
    WARP_VARS();
    ACC_INIT();

    const uint32_t* srcA0 = g_Wp + (size_t)0 * MQK + m0;
    const uint32_t* srcB0 = g_xk + (size_t)b * (CH / 2) * NPADC + n0;

    PIPE_LOOP(CH / 32, MQK, NPADC)

    uint32_t* outp = g_QKp + (size_t)b * 256 * NPADC;
#pragma unroll
    for (int i = 0; i < 2; i++) {
        int m_lo = m0 + warp_m * 32 + i * 16 + r;       // (m&15)==r<8
        int pg = (m_lo >> 4) * 8 + r;
        float b_lo = g_bias[m_lo], b_hi = g_bias[m_lo + 8];
#pragma unroll
        for (int j = 0; j < 8; j++) {
            int n = n0 + warp_n * 64 + j * 8 + 2 * cc;
            uint2 u;
            u.x = packbf(acc[i][j][0] + b_lo, acc[i][j][2] + b_hi);
            u.y = packbf(acc[i][j][1] + b_lo, acc[i][j][3] + b_hi);
            *reinterpret_cast<uint2*>(&outp[(size_t)pg * NPADC + n]) = u;
        }
    }
}

// =====================================================================
// GEMM2: P = (Q^T K)*scale*fg -> bf16 pairs [b][n][mp] + fused row stats
// =====================================================================
__global__ __launch_bounds__(256, 2) void gemm2_kernel(const float* __restrict__ fg) {
    __shared__ uint32_t As[2][16][136];
    __shared__ uint32_t Bs[2][16][136];
    const int b  = blockIdx.z;
    const int n0 = blockIdx.y * 128;
    const int m0 = blockIdx.x * 128;
    WARP_VARS();
    ACC_INIT();

    const uint32_t* srcA0 = g_QKp + (size_t)b * 256 * NPADC + n0;                   // Q pair rows 0..127
    const uint32_t* srcB0 = g_QKp + ((size_t)b * 256 + 128) * NPADC + m0;           // K pair rows

    PIPE_LOOP(CK / 32, NPADC, NPADC)

    const float* FG = fg + (size_t)b * NN * NN;
    uint32_t* Pp = g_P + (size_t)b * NN * NPP;
#pragma unroll
    for (int i = 0; i < 2; i++)
#pragma unroll
        for (int h = 0; h < 2; h++) {
            int gn = n0 + warp_m * 32 + i * 16 + r + h * 8;
            bool rowvalid = gn < NN;
            size_t rowoff = (size_t)gn * NN;
            float mn = FLT_MAX, s1 = 0.f, s2 = 0.f;
#pragma unroll
            for (int j = 0; j < 8; j++) {
                int gm = m0 + warp_n * 64 + j * 8 + 2 * cc;
                if (rowvalid && gm < NN) {
                    float f0 = FG[rowoff + gm];
                    float p0 = acc[i][j][2 * h] * SCALE * f0;
                    mn = fminf(mn, p0); s1 += p0 * f0; s2 += f0;
                    float p1 = 0.f;
                    if (gm + 1 < NN) {
                        float f1 = FG[rowoff + gm + 1];
                        p1 = acc[i][j][2 * h + 1] * SCALE * f1;
                        mn = fminf(mn, p1); s1 += p1 * f1; s2 += f1;
                    }
                    Pp[(size_t)gn * NPP + (gm >> 1)] = packbf(p0, p1);
                }
            }
            mn = fminf(mn, __shfl_xor_sync(0xffffffffu, mn, 1));
            mn = fminf(mn, __shfl_xor_sync(0xffffffffu, mn, 2));
            s1 += __shfl_xor_sync(0xffffffffu, s1, 1);
            s1 += __shfl_xor_sync(0xffffffffu, s1, 2);
            s2 += __shfl_xor_sync(0xffffffffu, s2, 1);
            s2 += __shfl_xor_sync(0xffffffffu, s2, 2);
            if (cc == 0 && rowvalid) {
                atomicMinFloat(&g_minv[b * NN + gn], mn);
                atomicAdd(&g_s1[b * NN + gn], s1);
                atomicAdd(&g_s2[b * NN + gn], s2);
            }
        }
}

// =====================================================================
// simf: sim_final = (P - min)*fg*inv + bg -> bf16 pairs TRANSPOSED [b][mp][n]
// =====================================================================
__global__ void simf_kernel(const float* __restrict__ fg, const float* __restrict__ bg) {
    __shared__ uint32_t T[32][33];
    __shared__ float sMin[32], sInv[32];
    const int mp0 = blockIdx.x * 32;          // 27 tiles
    const int n0  = blockIdx.y * 32;          // 53 tiles -> 1696
    const int b   = blockIdx.z;
    const int tx = threadIdx.x, ty = threadIdx.y;
    const int tid = ty * 32 + tx;

    if (tid < 32) {
        int n = n0 + tid;
        if (n < NN) {
            float mn = g_minv[b * NN + n];
            sMin[tid] = mn;
            sInv[tid] = 1.f / (g_s1[b * NN + n] - mn * g_s2[b * NN + n] + EPSV);
        } else {
            sMin[tid] = 0.f; sInv[tid] = 0.f;
        }
    }
    __syncthreads();

    const float* FG = fg + (size_t)b * NN * NN;
    const float* BG = bg + (size_t)b * NN * NN;
    const uint32_t* Pp = g_P + (size_t)b * NN * NPP;
#pragma unroll
    for (int p = 0; p < 4; p++) {
        int ny = p * 8 + ty;
        int n = n0 + ny;
        int mp = mp0 + tx, m = 2 * mp;
        float v0 = 0.f, v1 = 0.f;
        if (n < NN && m < NN) {
            float2 pv = unpackbf(Pp[(size_t)n * NPP + mp]);
            size_t a = (size_t)n * NN + m;
            float mn = sMin[ny], inv = sInv[ny];
            if (m + 1 < NN) {
                float2 f2 = *reinterpret_cast<const float2*>(&FG[a & ~(size_t)0]);
                // unaligned-safe scalar path when a odd
                float fg0 = FG[a], fg1 = FG[a + 1];
                float bg0 = BG[a], bg1 = BG[a + 1];
                (void)f2;
                v0 = (pv.x - mn) * fg0 * inv + bg0;
                v1 = (pv.y - mn) * fg1 * inv + bg1;
            } else {
                v0 = (pv.x - mn) * FG[a] * inv + BG[a];
            }
        }
        T[tx][ny] = packbf(v0, v1);
    }
    __syncthreads();
#pragma unroll
    for (int p = 0; p < 4; p++) {
        int row = p * 8 + ty;                 // mp-local
        g_simfT[((size_t)b * NPP + mp0 + row) * NPADC + n0 + tx] = T[row][tx];
    }
}

// =====================================================================
// GEMM3 (transposed): out[c][n] = gamma * sum_m V_pair @ simf_T + x[c][n]
// =====================================================================
__global__ __launch_bounds__(256, 2) void gemm3_kernel(const float* __restrict__ x,
                                                       const float* __restrict__ gamma,
                                                       float* __restrict__ out) {
    __shared__ uint32_t As[2][16][136];
    __shared__ uint32_t Bs[2][16][136];
    const int b  = blockIdx.z;
    const int c0 = blockIdx.x * 128;
    const int n0 = blockIdx.y * 128;
    WARP_VARS();
    ACC_INIT();

    const uint32_t* srcA0 = g_xvT   + (size_t)b * NPP * CH + c0;
    const uint32_t* srcB0 = g_simfT + (size_t)b * NPP * NPADC + n0;

    PIPE_LOOP(53, CH, NPADC)   // 53*16 = 848 pair rows >= ceil(1681/2)

    const float g = gamma[0];
    const float* xf = x + (size_t)b * CH * NN;
    float* outb = out + (size_t)b * CH * NN;
#pragma unroll
    for (int i = 0; i < 2; i++)
#pragma unroll
        for (int h = 0; h < 2; h++) {
            int gc = c0 + warp_m * 32 + i * 16 + r + h * 8;
            size_t rowoff = (size_t)gc * NN;
#pragma unroll
            for (int j = 0; j < 8; j++) {
                int gn = n0 + warp_n * 64 + j * 8 + 2 * cc;
                if (gn < NN)
                    outb[rowoff + gn]     = g * acc[i][j][2 * h]     + xf[rowoff + gn];
                if (gn + 1 < NN)
                    outb[rowoff + gn + 1] = g * acc[i][j][2 * h + 1] + xf[rowoff + gn + 1];
            }
        }
}

// ---------------- launch ----------------
extern "C" void kernel_launch(void* const* d_in, const int* in_sizes, int n_in,
                              void* d_out, int out_size) {
    const float* x     = (const float*)d_in[0];
    const float* fg    = (const float*)d_in[1];
    const float* bg    = (const float*)d_in[2];
    const float* Wq    = (const float*)d_in[3];
    const float* bq    = (const float*)d_in[4];
    const float* Wk    = (const float*)d_in[5];
    const float* bk    = (const float*)d_in[6];
    const float* gamma = (const float*)d_in[7];
    float* out = (float*)d_out;

    pack_misc_kernel<<<((CH / 2) * MQK + 255) / 256, 256>>>(Wq, bq, Wk, bk);
    pack_xk_kernel<<<dim3(7, CH / 2, BATCH), 256>>>(x);
    pack_xvT_kernel<<<dim3(27, 16, BATCH), dim3(32, 8)>>>(x);

    gemm1_kernel<<<dim3(14, 4, BATCH), 256>>>();
    gemm2_kernel<<<dim3(14, 14, BATCH), 256>>>(fg);
    simf_kernel<<<dim3(27, 53, BATCH), dim3(32, 8)>>>(fg, bg);
    gemm3_kernel<<<dim3(4, 14, BATCH), 256>>>(x, gamma, out);
}